// round 4
// baseline (speedup 1.0000x reference)
#include <cuda_runtime.h>
#include <cstdint>

#define NT      512
#define IMGW    128
#define PIX     16384
#define NB      64
#define NSAMP   1024
#define NV      778

// ---------------- device scratch (no allocations allowed) ----------------
__device__ float4 g_samp[NB * NSAMP];     // xyz + 0.5*|s|^2
__device__ float  g_vmin[NB * 2 * NV];    // per-(batch,slice) vert mins
__device__ float  g_ssum[NB * 2];         // per-(batch,slice) sample-min sums

// ---------------- tf32 round-to-nearest-even (cuBLAS operand rounding) ----
__device__ __forceinline__ float tf32r(float x) {
    uint32_t u = __float_as_uint(x);
    uint32_t r = (u + 0xFFFu + ((u >> 13) & 1u)) & ~0x1FFFu;
    return __uint_as_float(r);
}

// ------- threefry2x32-20, JAX partitionable counter-mode, key = (0,1) -----
// Element e uses 64-bit counter e: x0 = hi(e) = 0, x1 = lo(e) = e.
// 32-bit sample = out0 ^ out1.
__device__ __forceinline__ uint32_t rotl32(uint32_t x, uint32_t d) {
    return (x << d) | (x >> (32u - d));
}

__device__ __forceinline__ uint32_t threefry_bits_part(uint32_t e) {
    uint32_t x0 = 0u;
    uint32_t x1 = e;
    const uint32_t k0 = 0u, k1 = 1u;
    const uint32_t k2 = 0x1BD11BDAu ^ k0 ^ k1;
    x0 += k0; x1 += k1;
#define TF_RND(r) { x0 += x1; x1 = rotl32(x1, r) ^ x0; }
    TF_RND(13u) TF_RND(15u) TF_RND(26u) TF_RND(6u)
    x0 += k1; x1 += k2 + 1u;
    TF_RND(17u) TF_RND(29u) TF_RND(16u) TF_RND(24u)
    x0 += k2; x1 += k0 + 2u;
    TF_RND(13u) TF_RND(15u) TF_RND(26u) TF_RND(6u)
    x0 += k0; x1 += k1 + 3u;
    TF_RND(17u) TF_RND(29u) TF_RND(16u) TF_RND(24u)
    x0 += k1; x1 += k2 + 4u;
    TF_RND(13u) TF_RND(15u) TF_RND(26u) TF_RND(6u)
    x0 += k2; x1 += k0 + 5u;
#undef TF_RND
    return x0 ^ x1;
}

// ---------------- pixel -> normalized xyz (+ 0.5*|s|^2) ----------------
// sp layout: [0..5] tf32-rounded Minv rows 0,1 ; [6..8] center ; [9..11] cube/2
__device__ __forceinline__ float4 pix_xyz4(int p, float imgval, const float* sp) {
    float tj = 2.0f * (float)(p & 127) / 127.0f - 1.0f;
    float ti = 2.0f * (float)(p >> 7)  / 127.0f - 1.0f;
    float u = (tj + 1.0f) * 64.0f;
    float v = (ti + 1.0f) * 64.0f;
    float d = imgval * sp[11] + sp[8];
    float ut = tf32r(u), vt = tf32r(v);
    float uw = fmaf(sp[0], ut, fmaf(sp[1], vt, sp[2]));
    float vw = fmaf(sp[3], ut, fmaf(sp[4], vt, sp[5]));
    float x = (uw - 320.0f) * d / 588.03f;
    float y = (vw - 240.0f) * d / 587.07f;   // FLIP = 1
    float xn = (x - sp[6]) / sp[9];
    float yn = (y - sp[7]) / sp[10];
    float zn = (d - sp[8]) / sp[11];
    float hs = 0.5f * (xn * xn + yn * yn + zn * zn);
    return make_float4(xn, yn, zn, hs);
}

// ---------------- block-wide threshold finder on a 4096 histogram -------
// finds T with count(buckets>T) < target <= count(>T) + hist[T]
__device__ void find_threshold(const uint32_t* hist, uint32_t target,
                               uint32_t* out_T, uint32_t* out_need,
                               uint32_t* scanbuf) {
    int tid = threadIdx.x;
    uint32_t c = 0;
#pragma unroll
    for (int k = 0; k < 8; k++) c += hist[tid * 8 + k];
    scanbuf[tid] = c;
    __syncthreads();
    for (int off = 1; off < NT; off <<= 1) {
        uint32_t v = scanbuf[tid];
        uint32_t add = (tid + off < NT) ? scanbuf[tid + off] : 0u;
        __syncthreads();
        scanbuf[tid] = v + add;
        __syncthreads();
    }
    uint32_t incl  = scanbuf[tid];
    uint32_t above = (tid + 1 < NT) ? scanbuf[tid + 1] : 0u;
    if (above < target && incl >= target) {
        uint32_t cgt = above;
        for (int k = 7; k >= 0; k--) {
            uint32_t h = hist[tid * 8 + k];
            if (cgt + h >= target) {
                *out_T = (uint32_t)(tid * 8 + k);
                *out_need = target - cgt;
                break;
            }
            cgt += h;
        }
    }
    __syncthreads();
}

// ================= K1: per-batch exact top-1024 selection =================
__global__ void __launch_bounds__(NT)
k_select(const float* __restrict__ real, const float* __restrict__ center,
         const float* __restrict__ Mmat, const float* __restrict__ cube) {
    extern __shared__ uint32_t smem_u32[];
    uint32_t* skey = smem_u32;          // PIX entries
    uint32_t* hist = smem_u32 + PIX;    // 4096 entries
    __shared__ uint32_t s_scan[NT];
    __shared__ float    s_par[12];
    __shared__ uint32_t s_T, s_need, s_L, s_need2, s_ntie;
    __shared__ uint32_t s_tie[64];

    int b = blockIdx.x;
    int tid = threadIdx.x;

    if (tid == 0) {
        const float* Mb = Mmat + b * 9;
        double a00 = Mb[0], a01 = Mb[1], a02 = Mb[2];
        double a10 = Mb[3], a11 = Mb[4], a12 = Mb[5];
        double a20 = Mb[6], a21 = Mb[7], a22 = Mb[8];
        double det = a00 * (a11 * a22 - a12 * a21)
                   - a01 * (a10 * a22 - a12 * a20)
                   + a02 * (a10 * a21 - a11 * a20);
        double inv = 1.0 / det;
        s_par[0] = tf32r((float)( (a11 * a22 - a12 * a21) * inv));
        s_par[1] = tf32r((float)(-(a01 * a22 - a02 * a21) * inv));
        s_par[2] = tf32r((float)( (a01 * a12 - a02 * a11) * inv));
        s_par[3] = tf32r((float)(-(a10 * a22 - a12 * a20) * inv));
        s_par[4] = tf32r((float)( (a00 * a22 - a02 * a20) * inv));
        s_par[5] = tf32r((float)(-(a00 * a12 - a02 * a10) * inv));
        s_par[6] = center[b * 3 + 0];
        s_par[7] = center[b * 3 + 1];
        s_par[8] = center[b * 3 + 2];
        s_par[9]  = cube[b * 3 + 0] * 0.5f;
        s_par[10] = cube[b * 3 + 1] * 0.5f;
        s_par[11] = cube[b * 3 + 2] * 0.5f;
        s_ntie = 0;
    }
    for (int i = tid; i < 4096; i += NT) hist[i] = 0;
    __syncthreads();

    const float* img = real + b * PIX;

    // pass 1: keys + coarse histogram (bucket = key >> 12)
    for (int p = tid; p < PIX; p += NT) {
        uint32_t bits = threefry_bits_part((uint32_t)(b * PIX + p));
        bool valid = img[p] <= 0.99f;
        uint32_t sk = valid ? ((bits >> 9) | 0x800000u) : 0u;
        skey[p] = sk;
        if (valid) atomicAdd(&hist[sk >> 12], 1u);
    }
    __syncthreads();

    find_threshold(hist, (uint32_t)NSAMP, &s_T, &s_need, s_scan);

    // pass 2: fine histogram inside threshold bucket (low 12 bits)
    for (int i = tid; i < 4096; i += NT) hist[i] = 0;
    __syncthreads();
    uint32_t T = s_T;
    for (int p = tid; p < PIX; p += NT) {
        uint32_t sk = skey[p];
        if ((sk >> 12) == T) atomicAdd(&hist[sk & 0xFFFu], 1u);
    }
    __syncthreads();

    find_threshold(hist, s_need, &s_L, &s_need2, s_scan);
    uint32_t thrkey = (s_T << 12) | s_L;
    uint32_t need2  = s_need2;

    // pass 3: deterministic compaction of strictly-greater keys
    const int PPT = PIX / NT;  // 32 contiguous pixels per thread
    int base = tid * PPT;
    uint32_t cnt = 0;
    for (int k = 0; k < PPT; k++) cnt += (skey[base + k] > thrkey) ? 1u : 0u;
    s_scan[tid] = cnt;
    __syncthreads();
    for (int off = 1; off < NT; off <<= 1) {
        uint32_t v = s_scan[tid];
        uint32_t add = (tid >= off) ? s_scan[tid - off] : 0u;
        __syncthreads();
        s_scan[tid] = v + add;
        __syncthreads();
    }
    uint32_t offset = s_scan[tid] - cnt;  // exclusive prefix
    float4* out = g_samp + b * NSAMP;
    for (int k = 0; k < PPT; k++) {
        int p = base + k;
        uint32_t sk = skey[p];
        if (sk > thrkey) {
            out[offset++] = pix_xyz4(p, img[p], s_par);
        } else if (sk == thrkey) {
            uint32_t pos = atomicAdd(&s_ntie, 1u);
            if (pos < 64u) s_tie[pos] = (uint32_t)p;
        }
    }
    __syncthreads();

    // boundary ties: JAX top_k prefers lower index -> sort, take first need2
    if (tid == 0) {
        uint32_t n = s_ntie < 64u ? s_ntie : 64u;
        for (uint32_t i = 1; i < n; i++) {
            uint32_t key = s_tie[i];
            int j = (int)i - 1;
            while (j >= 0 && s_tie[j] > key) { s_tie[j + 1] = s_tie[j]; j--; }
            s_tie[j + 1] = key;
        }
        uint32_t start = NSAMP - need2;
        for (uint32_t i = 0; i < need2 && i < n; i++) {
            uint32_t p = s_tie[i];
            out[start + i] = pix_xyz4((int)p, img[p], s_par);
        }
    }
}

// ====== K2: chamfer distances, one CTA per (batch, 512-sample slice) ======
__global__ void __launch_bounds__(NT)
k_dist(const float* __restrict__ verts) {
    __shared__ float4 sv[NV];
    __shared__ float4 ss[NT];
    __shared__ float  sred[NT];

    int blk = blockIdx.x;
    int b = blk >> 1;
    int slice = blk & 1;
    int tid = threadIdx.x;

    const float* vb = verts + b * NV * 3;
    for (int k = tid; k < NV; k += NT) {
        float x = vb[3 * k], y = vb[3 * k + 1], z = vb[3 * k + 2];
        sv[k] = make_float4(x, y, z, 0.5f * (x * x + y * y + z * z));
    }
    const float4* sp = g_samp + b * NSAMP + slice * NT;
    ss[tid] = sp[tid];
    __syncthreads();

    // vert pass: min over this CTA's 512 samples, per vert
    for (int tile = 0; tile < 2; tile++) {
        int v = tile * NT + tid;
        if (v < NV) {
            float4 vv = sv[v];
            float m0 = 1e30f, m1 = 1e30f, m2 = 1e30f, m3 = 1e30f;
#pragma unroll 2
            for (int s = 0; s < NT; s += 4) {
                float4 a = ss[s];
                float4 c = ss[s + 1];
                float4 d = ss[s + 2];
                float4 e = ss[s + 3];
                m0 = fminf(m0, fmaf(-vv.x, a.x, fmaf(-vv.y, a.y, fmaf(-vv.z, a.z, a.w))));
                m1 = fminf(m1, fmaf(-vv.x, c.x, fmaf(-vv.y, c.y, fmaf(-vv.z, c.z, c.w))));
                m2 = fminf(m2, fmaf(-vv.x, d.x, fmaf(-vv.y, d.y, fmaf(-vv.z, d.z, d.w))));
                m3 = fminf(m3, fmaf(-vv.x, e.x, fmaf(-vv.y, e.y, fmaf(-vv.z, e.z, e.w))));
            }
            float m = fminf(fminf(m0, m1), fminf(m2, m3));
            g_vmin[blk * NV + v] = 2.0f * (m + vv.w);
        }
    }

    // sample pass: min over all 778 verts, per sample (one per thread)
    float4 me = ss[tid];
    float m0 = 1e30f, m1 = 1e30f;
#pragma unroll 2
    for (int v = 0; v < NV; v += 2) {  // NV = 778 (even)
        float4 a = sv[v];
        float4 c = sv[v + 1];
        m0 = fminf(m0, fmaf(-me.x, a.x, fmaf(-me.y, a.y, fmaf(-me.z, a.z, a.w))));
        m1 = fminf(m1, fmaf(-me.x, c.x, fmaf(-me.y, c.y, fmaf(-me.z, c.z, c.w))));
    }
    float d2min = 2.0f * (fminf(m0, m1) + me.w);

    // deterministic block sum of sample mins
    sred[tid] = d2min;
    __syncthreads();
    for (int off = NT / 2; off > 0; off >>= 1) {
        if (tid < off) sred[tid] += sred[tid + off];
        __syncthreads();
    }
    if (tid == 0) g_ssum[blk] = sred[0];
}

// ================= K3: final deterministic reduction =================
__global__ void __launch_bounds__(NT)
k_reduce(float* __restrict__ out) {
    __shared__ float sred[NT];
    __shared__ float s_a;
    int tid = threadIdx.x;

    float acc1 = 0.0f;
    if (tid < NB * 2) acc1 = g_ssum[tid];
    sred[tid] = acc1;
    __syncthreads();
    for (int off = NT / 2; off > 0; off >>= 1) {
        if (tid < off) sred[tid] += sred[tid + off];
        __syncthreads();
    }
    if (tid == 0) s_a = sred[0];
    __syncthreads();

    float acc2 = 0.0f;
    for (int idx = tid; idx < NB * NV; idx += NT) {
        int b = idx / NV;
        int v = idx - b * NV;
        acc2 += fminf(g_vmin[(2 * b) * NV + v], g_vmin[(2 * b + 1) * NV + v]);
    }
    sred[tid] = acc2;
    __syncthreads();
    for (int off = NT / 2; off > 0; off >>= 1) {
        if (tid < off) sred[tid] += sred[tid + off];
        __syncthreads();
    }
    if (tid == 0) {
        out[0] = s_a / (float)(NB * NSAMP) + sred[0] / (float)(NB * NV);
    }
}

// ======================== launch ========================
extern "C" void kernel_launch(void* const* d_in, const int* in_sizes, int n_in,
                              void* d_out, int out_size) {
    const float* real   = (const float*)d_in[0];
    // d_in[1] synth unused, d_in[3] faces unused
    const float* verts  = (const float*)d_in[2];
    const float* center = (const float*)d_in[4];
    const float* Mmat   = (const float*)d_in[5];
    const float* cube   = (const float*)d_in[6];

    size_t smem1 = (size_t)(PIX + 4096) * sizeof(uint32_t);  // 80 KB dynamic
    cudaFuncSetAttribute(k_select, cudaFuncAttributeMaxDynamicSharedMemorySize,
                         (int)smem1);

    k_select<<<NB, NT, smem1>>>(real, center, Mmat, cube);
    k_dist<<<NB * 2, NT>>>(verts);
    k_reduce<<<1, NT>>>((float*)d_out);
}

// round 5
// speedup vs baseline: 1.1732x; 1.1732x over previous
#include <cuda_runtime.h>
#include <cstdint>

#define NT      512
#define PIX     16384
#define NB      64
#define NSAMP   1024
#define NV      778
#define NSLICE  4
#define SLICE   256      // NSAMP / NSLICE

// ---------------- device scratch (no allocations allowed) ----------------
__device__ uint32_t g_keys[NB * PIX];        // 4 MB: per-pixel selection keys
__device__ uint32_t g_hist[NB * 4096];       // 1 MB: per-batch 12-bit histograms
__device__ float4   g_samp[NB * NSAMP];      // xyz + 0.5*|s|^2
__device__ float    g_vmin[NB * NSLICE * NV];// per-(batch,slice) vert mins (already 2*(m+w))
__device__ float    g_ssum[NB * NSLICE];     // per-(batch,slice) sample-min sums
__device__ float    g_batv[NB];              // per-batch vert-min sums

// ---------------- tf32 round-to-nearest-even (cuBLAS operand rounding) ----
__device__ __forceinline__ float tf32r(float x) {
    uint32_t u = __float_as_uint(x);
    uint32_t r = (u + 0xFFFu + ((u >> 13) & 1u)) & ~0x1FFFu;
    return __uint_as_float(r);
}

// ------- threefry2x32-20, JAX partitionable counter-mode, key = (0,1) -----
__device__ __forceinline__ uint32_t rotl32(uint32_t x, uint32_t d) {
    return (x << d) | (x >> (32u - d));
}

__device__ __forceinline__ uint32_t threefry_bits_part(uint32_t e) {
    uint32_t x0 = 0u;
    uint32_t x1 = e;
    const uint32_t k0 = 0u, k1 = 1u;
    const uint32_t k2 = 0x1BD11BDAu ^ k0 ^ k1;
    x0 += k0; x1 += k1;
#define TF_RND(r) { x0 += x1; x1 = rotl32(x1, r) ^ x0; }
    TF_RND(13u) TF_RND(15u) TF_RND(26u) TF_RND(6u)
    x0 += k1; x1 += k2 + 1u;
    TF_RND(17u) TF_RND(29u) TF_RND(16u) TF_RND(24u)
    x0 += k2; x1 += k0 + 2u;
    TF_RND(13u) TF_RND(15u) TF_RND(26u) TF_RND(6u)
    x0 += k0; x1 += k1 + 3u;
    TF_RND(17u) TF_RND(29u) TF_RND(16u) TF_RND(24u)
    x0 += k1; x1 += k2 + 4u;
    TF_RND(13u) TF_RND(15u) TF_RND(26u) TF_RND(6u)
    x0 += k2; x1 += k0 + 5u;
#undef TF_RND
    return x0 ^ x1;
}

// ---------------- pixel -> normalized xyz (+ 0.5*|s|^2) ----------------
// sp layout: [0..5] tf32-rounded Minv rows 0,1 ; [6..8] center ; [9..11] cube/2
__device__ __forceinline__ float4 pix_xyz4(int p, float imgval, const float* sp) {
    float tj = 2.0f * (float)(p & 127) / 127.0f - 1.0f;
    float ti = 2.0f * (float)(p >> 7)  / 127.0f - 1.0f;
    float u = (tj + 1.0f) * 64.0f;
    float v = (ti + 1.0f) * 64.0f;
    float d = imgval * sp[11] + sp[8];
    float ut = tf32r(u), vt = tf32r(v);
    float uw = fmaf(sp[0], ut, fmaf(sp[1], vt, sp[2]));
    float vw = fmaf(sp[3], ut, fmaf(sp[4], vt, sp[5]));
    float x = (uw - 320.0f) * d / 588.03f;
    float y = (vw - 240.0f) * d / 587.07f;   // FLIP = 1
    float xn = (x - sp[6]) / sp[9];
    float yn = (y - sp[7]) / sp[10];
    float zn = (d - sp[8]) / sp[11];
    float hs = 0.5f * (xn * xn + yn * yn + zn * zn);
    return make_float4(xn, yn, zn, hs);
}

// ================= K0: zero the global histograms =================
__global__ void __launch_bounds__(NT)
k_zero() {
    int i = blockIdx.x * NT + threadIdx.x;
    if (i < NB * 4096) g_hist[i] = 0u;
}

// ===== KA: full-chip threefry key-gen + global histogram (grid 1024) =====
__global__ void __launch_bounds__(256)
kA(const float* __restrict__ real) {
    int gt = blockIdx.x * 256 + threadIdx.x;   // 0..262143
#pragma unroll
    for (int k = 0; k < 4; k++) {
        uint32_t e = (uint32_t)gt + (uint32_t)k * 262144u;  // 0..2^20-1
        uint32_t bits = threefry_bits_part(e);
        bool valid = real[e] <= 0.99f;
        uint32_t sk = valid ? ((bits >> 9) | 0x800000u) : 0u;
        g_keys[e] = sk;
        if (valid)
            atomicAdd(&g_hist[(e >> 14) * 4096u + ((sk >> 11) & 0xFFFu)], 1u);
    }
}

// ---------------- block-wide threshold finder on a 4096 histogram -------
// finds T with count(buckets>T) < target <= count(>T) + hist[T]
__device__ void find_threshold(const uint32_t* hist, uint32_t target,
                               uint32_t* out_T, uint32_t* out_need,
                               uint32_t* scanbuf) {
    int tid = threadIdx.x;
    uint32_t c = 0;
#pragma unroll
    for (int k = 0; k < 8; k++) c += hist[tid * 8 + k];
    scanbuf[tid] = c;
    __syncthreads();
    for (int off = 1; off < NT; off <<= 1) {
        uint32_t v = scanbuf[tid];
        uint32_t add = (tid + off < NT) ? scanbuf[tid + off] : 0u;
        __syncthreads();
        scanbuf[tid] = v + add;
        __syncthreads();
    }
    uint32_t incl  = scanbuf[tid];
    uint32_t above = (tid + 1 < NT) ? scanbuf[tid + 1] : 0u;
    if (above < target && incl >= target) {
        uint32_t cgt = above;
        for (int k = 7; k >= 0; k--) {
            uint32_t h = hist[tid * 8 + k];
            if (cgt + h >= target) {
                *out_T = (uint32_t)(tid * 8 + k);
                *out_need = target - cgt;
                break;
            }
            cgt += h;
        }
    }
    __syncthreads();
}

// ===== KB: per-batch select + transform using prebuilt keys/hist =====
__global__ void __launch_bounds__(NT)
kB(const float* __restrict__ real, const float* __restrict__ center,
   const float* __restrict__ Mmat, const float* __restrict__ cube) {
    extern __shared__ uint32_t smem_u32[];
    uint32_t* skey = smem_u32;          // PIX entries (64 KB)
    uint32_t* hist = smem_u32 + PIX;    // 4096 entries (16 KB)
    __shared__ uint32_t s_scan[NT];
    __shared__ float    s_par[12];
    __shared__ uint32_t s_T, s_need, s_ntie;
    __shared__ uint32_t s_tie[256];

    int b = blockIdx.x;
    int tid = threadIdx.x;

    if (tid == 0) {
        const float* Mb = Mmat + b * 9;
        double a00 = Mb[0], a01 = Mb[1], a02 = Mb[2];
        double a10 = Mb[3], a11 = Mb[4], a12 = Mb[5];
        double a20 = Mb[6], a21 = Mb[7], a22 = Mb[8];
        double det = a00 * (a11 * a22 - a12 * a21)
                   - a01 * (a10 * a22 - a12 * a20)
                   + a02 * (a10 * a21 - a11 * a20);
        double inv = 1.0 / det;
        s_par[0] = tf32r((float)( (a11 * a22 - a12 * a21) * inv));
        s_par[1] = tf32r((float)(-(a01 * a22 - a02 * a21) * inv));
        s_par[2] = tf32r((float)( (a01 * a12 - a02 * a11) * inv));
        s_par[3] = tf32r((float)(-(a10 * a22 - a12 * a20) * inv));
        s_par[4] = tf32r((float)( (a00 * a22 - a02 * a20) * inv));
        s_par[5] = tf32r((float)(-(a00 * a12 - a02 * a10) * inv));
        s_par[6] = center[b * 3 + 0];
        s_par[7] = center[b * 3 + 1];
        s_par[8] = center[b * 3 + 2];
        s_par[9]  = cube[b * 3 + 0] * 0.5f;
        s_par[10] = cube[b * 3 + 1] * 0.5f;
        s_par[11] = cube[b * 3 + 2] * 0.5f;
        s_ntie = 0;
    }

    // load this batch's histogram + keys into smem (coalesced, L2-resident)
    for (int i = tid; i < 4096; i += NT) hist[i] = g_hist[b * 4096 + i];
    const uint4* gk = (const uint4*)(g_keys + b * PIX);
    uint4* sk4 = (uint4*)skey;
    for (int i = tid; i < PIX / 4; i += NT) sk4[i] = gk[i];
    __syncthreads();

    find_threshold(hist, (uint32_t)NSAMP, &s_T, &s_need, s_scan);
    uint32_t thrRaw = 4096u + s_T;     // bucket id in (sk >> 11) space
    uint32_t need   = s_need;

    // deterministic compaction of strictly-greater-bucket keys
    const int PPT = PIX / NT;  // 32 contiguous pixels per thread
    int base = tid * PPT;
    uint32_t cnt = 0;
#pragma unroll 4
    for (int k = 0; k < PPT; k++) cnt += ((skey[base + k] >> 11) > thrRaw) ? 1u : 0u;
    s_scan[tid] = cnt;
    __syncthreads();
    for (int off = 1; off < NT; off <<= 1) {
        uint32_t v = s_scan[tid];
        uint32_t add = (tid >= off) ? s_scan[tid - off] : 0u;
        __syncthreads();
        s_scan[tid] = v + add;
        __syncthreads();
    }
    uint32_t offset = s_scan[tid] - cnt;  // exclusive prefix
    const float* img = real + b * PIX;
    float4* out = g_samp + b * NSAMP;
    for (int k = 0; k < PPT; k++) {
        int p = base + k;
        uint32_t raw = skey[p] >> 11;
        if (raw > thrRaw) {
            out[offset++] = pix_xyz4(p, img[p], s_par);
        } else if (raw == thrRaw) {
            uint32_t pos = atomicAdd(&s_ntie, 1u);
            if (pos < 256u) s_tie[pos] = (uint32_t)p;
        }
    }
    __syncthreads();

    // boundary bucket: sort candidates by (key desc, index asc), take `need`
    if (tid == 0) {
        uint32_t n = s_ntie < 256u ? s_ntie : 256u;
        for (uint32_t i = 1; i < n; i++) {
            uint32_t pi = s_tie[i];
            uint32_t ki = skey[pi];
            int j = (int)i - 1;
            while (j >= 0) {
                uint32_t pj = s_tie[j];
                uint32_t kj = skey[pj];
                if (kj < ki || (kj == ki && pj > pi)) {
                    s_tie[j + 1] = pj; j--;
                } else break;
            }
            s_tie[j + 1] = pi;
        }
        uint32_t start = NSAMP - need;
        for (uint32_t i = 0; i < need && i < n; i++) {
            uint32_t p = s_tie[i];
            out[start + i] = pix_xyz4((int)p, img[p], s_par);
        }
    }
}

// ===== K_VERT: per-vert min over one 256-sample slice (grid 256) =====
__global__ void __launch_bounds__(NT)
k_vert(const float* __restrict__ verts) {
    __shared__ float4 ss[SLICE];
    int blk = blockIdx.x;          // b*NSLICE + slice
    int b = blk >> 2;
    int slice = blk & 3;
    int tid = threadIdx.x;

    if (tid < SLICE) ss[tid] = g_samp[b * NSAMP + slice * SLICE + tid];
    __syncthreads();

    const float* vb = verts + b * NV * 3;
    int v1 = tid;
    int v2 = tid + NT;             // 512 + tid, valid if < 778
    bool has2 = v2 < NV;

    float4 a1, a2;
    {
        float x = vb[3 * v1], y = vb[3 * v1 + 1], z = vb[3 * v1 + 2];
        a1 = make_float4(x, y, z, 0.5f * (x * x + y * y + z * z));
    }
    if (has2) {
        float x = vb[3 * v2], y = vb[3 * v2 + 1], z = vb[3 * v2 + 2];
        a2 = make_float4(x, y, z, 0.5f * (x * x + y * y + z * z));
    } else {
        a2 = make_float4(0.f, 0.f, 0.f, 0.f);
    }

    float p0 = 1e30f, p1 = 1e30f, q0 = 1e30f, q1 = 1e30f;
#pragma unroll 4
    for (int s = 0; s < SLICE; s += 2) {
        float4 c = ss[s];
        float4 d = ss[s + 1];
        p0 = fminf(p0, fmaf(-a1.x, c.x, fmaf(-a1.y, c.y, fmaf(-a1.z, c.z, c.w))));
        p1 = fminf(p1, fmaf(-a1.x, d.x, fmaf(-a1.y, d.y, fmaf(-a1.z, d.z, d.w))));
        q0 = fminf(q0, fmaf(-a2.x, c.x, fmaf(-a2.y, c.y, fmaf(-a2.z, c.z, c.w))));
        q1 = fminf(q1, fmaf(-a2.x, d.x, fmaf(-a2.y, d.y, fmaf(-a2.z, d.z, d.w))));
    }
    g_vmin[blk * NV + v1] = 2.0f * (fminf(p0, p1) + a1.w);
    if (has2) g_vmin[blk * NV + v2] = 2.0f * (fminf(q0, q1) + a2.w);
}

// ===== K_SAMP: per-sample min over all verts, one slice/CTA (grid 256) =====
__global__ void __launch_bounds__(SLICE)
k_samp(const float* __restrict__ verts) {
    __shared__ float4 sv[NV];
    __shared__ float  sred[SLICE];
    int blk = blockIdx.x;          // b*NSLICE + slice
    int b = blk >> 2;
    int slice = blk & 3;
    int tid = threadIdx.x;

    const float* vb = verts + b * NV * 3;
    for (int k = tid; k < NV; k += SLICE) {
        float x = vb[3 * k], y = vb[3 * k + 1], z = vb[3 * k + 2];
        sv[k] = make_float4(x, y, z, 0.5f * (x * x + y * y + z * z));
    }
    float4 me = g_samp[b * NSAMP + slice * SLICE + tid];
    __syncthreads();

    float m0 = 1e30f, m1 = 1e30f;
#pragma unroll 2
    for (int v = 0; v < NV; v += 2) {   // NV = 778 (even)
        float4 a = sv[v];
        float4 c = sv[v + 1];
        m0 = fminf(m0, fmaf(-me.x, a.x, fmaf(-me.y, a.y, fmaf(-me.z, a.z, a.w))));
        m1 = fminf(m1, fmaf(-me.x, c.x, fmaf(-me.y, c.y, fmaf(-me.z, c.z, c.w))));
    }
    float d2min = 2.0f * (fminf(m0, m1) + me.w);

    sred[tid] = d2min;
    __syncthreads();
    for (int off = SLICE / 2; off > 0; off >>= 1) {
        if (tid < off) sred[tid] += sred[tid + off];
        __syncthreads();
    }
    if (tid == 0) g_ssum[blk] = sred[0];
}

// ===== K_RED1: per-batch combine slice vert-mins + sum (grid 64) =====
__global__ void __launch_bounds__(NT)
k_red1() {
    __shared__ float sred[NT];
    int b = blockIdx.x;
    int tid = threadIdx.x;

    float acc = 0.0f;
    for (int v = tid; v < NV; v += NT) {
        float m = fminf(fminf(g_vmin[(b * 4 + 0) * NV + v], g_vmin[(b * 4 + 1) * NV + v]),
                        fminf(g_vmin[(b * 4 + 2) * NV + v], g_vmin[(b * 4 + 3) * NV + v]));
        acc += m;
    }
    sred[tid] = acc;
    __syncthreads();
    for (int off = NT / 2; off > 0; off >>= 1) {
        if (tid < off) sred[tid] += sred[tid + off];
        __syncthreads();
    }
    if (tid == 0) g_batv[b] = sred[0];
}

// ===== K_RED2: final scalar (grid 1) =====
__global__ void __launch_bounds__(256)
k_red2(float* __restrict__ out) {
    __shared__ float sred[256];
    __shared__ float s_a;
    int tid = threadIdx.x;

    float a = (tid < NB * NSLICE) ? g_ssum[tid] : 0.0f;
    sred[tid] = a;
    __syncthreads();
    for (int off = 128; off > 0; off >>= 1) {
        if (tid < off) sred[tid] += sred[tid + off];
        __syncthreads();
    }
    if (tid == 0) s_a = sred[0];
    __syncthreads();

    float v = (tid < NB) ? g_batv[tid] : 0.0f;
    sred[tid] = v;
    __syncthreads();
    for (int off = 128; off > 0; off >>= 1) {
        if (tid < off) sred[tid] += sred[tid + off];
        __syncthreads();
    }
    if (tid == 0) {
        out[0] = s_a / (float)(NB * NSAMP) + sred[0] / (float)(NB * NV);
    }
}

// ======================== launch ========================
extern "C" void kernel_launch(void* const* d_in, const int* in_sizes, int n_in,
                              void* d_out, int out_size) {
    const float* real   = (const float*)d_in[0];
    // d_in[1] synth unused, d_in[3] faces unused
    const float* verts  = (const float*)d_in[2];
    const float* center = (const float*)d_in[4];
    const float* Mmat   = (const float*)d_in[5];
    const float* cube   = (const float*)d_in[6];

    size_t smemB = (size_t)(PIX + 4096) * sizeof(uint32_t);  // 80 KB dynamic
    cudaFuncSetAttribute(kB, cudaFuncAttributeMaxDynamicSharedMemorySize,
                         (int)smemB);

    k_zero<<<(NB * 4096 + NT - 1) / NT, NT>>>();
    kA<<<1024, 256>>>(real);
    kB<<<NB, NT, smemB>>>(real, center, Mmat, cube);
    k_vert<<<NB * NSLICE, NT>>>(verts);
    k_samp<<<NB * NSLICE, SLICE>>>(verts);
    k_red1<<<NB, NT>>>();
    k_red2<<<1, 256>>>((float*)d_out);
}

// round 6
// speedup vs baseline: 1.2314x; 1.0496x over previous
#include <cuda_runtime.h>
#include <cstdint>

#define NT      512
#define PIX     16384
#define NB      64
#define NSAMP   1024
#define NV      778
#define NPAIR   389      // NV/2
#define SLOTS   32
#define NVB     (NB * NV)

typedef unsigned long long ull;

// ---------------- device scratch (no allocations allowed) ----------------
__device__ uint32_t g_hist[NB * 4096];           // per-batch bucket counts
__device__ uint32_t g_bl[NB * 4096 * SLOTS];     // bucket entry lists (32 MB)
__device__ float4   g_samp[NB * NSAMP];          // xyz + 0.5*|s|^2
__device__ uint32_t g_vminb[NVB];                // bits of (d2min + 1.0f), atomicMin
__device__ float    g_ssum[NB * 8];              // per-(batch,slice) sample-min sums
__device__ float    g_batv[NB];                  // per-batch vert-min sums
__device__ float    g_bats[NB];                  // per-batch sample-min sums

// ---------------- tf32 round-to-nearest-even (cuBLAS operand rounding) ----
__device__ __forceinline__ float tf32r(float x) {
    uint32_t u = __float_as_uint(x);
    uint32_t r = (u + 0xFFFu + ((u >> 13) & 1u)) & ~0x1FFFu;
    return __uint_as_float(r);
}

// ---------------- packed f32x2 helpers ----------------
__device__ __forceinline__ ull pk2(float lo, float hi) {
    ull r;
    asm("mov.b64 %0, {%1, %2};" : "=l"(r) : "f"(lo), "f"(hi));
    return r;
}

// (nx*X + (ny*Y + (nz*Z + W))) on both lanes, returns (lo, hi)
__device__ __forceinline__ float2 dot3p(ull nx, ull X, ull ny, ull Y,
                                        ull nz, ull Z, ull W) {
    float lo, hi;
    asm("{\n\t"
        ".reg .b64 t;\n\t"
        "fma.rn.f32x2 t, %2, %3, %4;\n\t"
        "fma.rn.f32x2 t, %5, %6, t;\n\t"
        "fma.rn.f32x2 t, %7, %8, t;\n\t"
        "mov.b64 {%0, %1}, t;\n\t"
        "}"
        : "=f"(lo), "=f"(hi)
        : "l"(nz), "l"(Z), "l"(W), "l"(ny), "l"(Y), "l"(nx), "l"(X));
    return make_float2(lo, hi);
}

// ------- threefry2x32-20, JAX partitionable counter-mode, key = (0,1) -----
__device__ __forceinline__ uint32_t rotl32(uint32_t x, uint32_t d) {
    return (x << d) | (x >> (32u - d));
}

__device__ __forceinline__ uint32_t threefry_bits_part(uint32_t e) {
    uint32_t x0 = 0u;
    uint32_t x1 = e;
    const uint32_t k0 = 0u, k1 = 1u;
    const uint32_t k2 = 0x1BD11BDAu ^ k0 ^ k1;
    x0 += k0; x1 += k1;
#define TF_RND(r) { x0 += x1; x1 = rotl32(x1, r) ^ x0; }
    TF_RND(13u) TF_RND(15u) TF_RND(26u) TF_RND(6u)
    x0 += k1; x1 += k2 + 1u;
    TF_RND(17u) TF_RND(29u) TF_RND(16u) TF_RND(24u)
    x0 += k2; x1 += k0 + 2u;
    TF_RND(13u) TF_RND(15u) TF_RND(26u) TF_RND(6u)
    x0 += k0; x1 += k1 + 3u;
    TF_RND(17u) TF_RND(29u) TF_RND(16u) TF_RND(24u)
    x0 += k1; x1 += k2 + 4u;
    TF_RND(13u) TF_RND(15u) TF_RND(26u) TF_RND(6u)
    x0 += k2; x1 += k0 + 5u;
#undef TF_RND
    return x0 ^ x1;
}

// ---------------- pixel -> normalized xyz (+ 0.5*|s|^2) ----------------
__device__ __forceinline__ float4 pix_xyz4(int p, float imgval, const float* sp) {
    float tj = 2.0f * (float)(p & 127) / 127.0f - 1.0f;
    float ti = 2.0f * (float)(p >> 7)  / 127.0f - 1.0f;
    float u = (tj + 1.0f) * 64.0f;
    float v = (ti + 1.0f) * 64.0f;
    float d = imgval * sp[11] + sp[8];
    float ut = tf32r(u), vt = tf32r(v);
    float uw = fmaf(sp[0], ut, fmaf(sp[1], vt, sp[2]));
    float vw = fmaf(sp[3], ut, fmaf(sp[4], vt, sp[5]));
    float x = (uw - 320.0f) * d / 588.03f;
    float y = (vw - 240.0f) * d / 587.07f;   // FLIP = 1
    float xn = (x - sp[6]) / sp[9];
    float yn = (y - sp[7]) / sp[10];
    float zn = (d - sp[8]) / sp[11];
    float hs = 0.5f * (xn * xn + yn * yn + zn * zn);
    return make_float4(xn, yn, zn, hs);
}

// ================= K0: zero histograms + init vert-min to +inf =============
__global__ void __launch_bounds__(NT)
k_zero() {
    int i = blockIdx.x * NT + threadIdx.x;
    if (i < NB * 4096) g_hist[i] = 0u;
    else if (i < NB * 4096 + NVB) g_vminb[i - NB * 4096] = 0x7F800000u;
}

// ===== KA: full-chip threefry + bucket binning (grid 1024) =====
__global__ void __launch_bounds__(256)
kA(const float* __restrict__ real) {
    int gt = blockIdx.x * 256 + threadIdx.x;   // 0..262143
#pragma unroll
    for (int k = 0; k < 4; k++) {
        uint32_t e = (uint32_t)gt + (uint32_t)k * 262144u;  // 0..2^20-1
        uint32_t bits = threefry_bits_part(e);
        bool valid = real[e] <= 0.99f;
        if (valid) {
            uint32_t sk = bits >> 9;             // 23-bit key
            uint32_t bucket = sk >> 11;          // top 12 bits
            uint32_t low11  = sk & 0x7FFu;
            uint32_t bi = (e >> 14) * 4096u + bucket;
            uint32_t pos = atomicAdd(&g_hist[bi], 1u);
            if (pos < SLOTS)
                g_bl[bi * SLOTS + pos] = (low11 << 14) | (e & 16383u);
        }
    }
}

// ===== KC: per-batch threshold + selected-pixel transform (grid 64) =====
__global__ void __launch_bounds__(NT)
kC(const float* __restrict__ real, const float* __restrict__ center,
   const float* __restrict__ Mmat, const float* __restrict__ cube) {
    __shared__ uint32_t hist[4096];
    __shared__ uint32_t s_scan[NT];
    __shared__ float    s_par[12];
    __shared__ uint32_t s_T, s_need, s_cnt;

    int b = blockIdx.x;
    int tid = threadIdx.x;

    if (tid == 0) {
        const float* Mb = Mmat + b * 9;
        double a00 = Mb[0], a01 = Mb[1], a02 = Mb[2];
        double a10 = Mb[3], a11 = Mb[4], a12 = Mb[5];
        double a20 = Mb[6], a21 = Mb[7], a22 = Mb[8];
        double det = a00 * (a11 * a22 - a12 * a21)
                   - a01 * (a10 * a22 - a12 * a20)
                   + a02 * (a10 * a21 - a11 * a20);
        double inv = 1.0 / det;
        s_par[0] = tf32r((float)( (a11 * a22 - a12 * a21) * inv));
        s_par[1] = tf32r((float)(-(a01 * a22 - a02 * a21) * inv));
        s_par[2] = tf32r((float)( (a01 * a12 - a02 * a11) * inv));
        s_par[3] = tf32r((float)(-(a10 * a22 - a12 * a20) * inv));
        s_par[4] = tf32r((float)( (a00 * a22 - a02 * a20) * inv));
        s_par[5] = tf32r((float)(-(a00 * a12 - a02 * a10) * inv));
        s_par[6] = center[b * 3 + 0];
        s_par[7] = center[b * 3 + 1];
        s_par[8] = center[b * 3 + 2];
        s_par[9]  = cube[b * 3 + 0] * 0.5f;
        s_par[10] = cube[b * 3 + 1] * 0.5f;
        s_par[11] = cube[b * 3 + 2] * 0.5f;
        s_cnt = 0;
    }
    for (int i = tid; i < 4096; i += NT) hist[i] = g_hist[b * 4096 + i];
    __syncthreads();

    // threshold: suffix counts over 4096 buckets
    {
        uint32_t c = 0;
#pragma unroll
        for (int k = 0; k < 8; k++) c += hist[tid * 8 + k];
        s_scan[tid] = c;
        __syncthreads();
        for (int off = 1; off < NT; off <<= 1) {
            uint32_t v = s_scan[tid];
            uint32_t add = (tid + off < NT) ? s_scan[tid + off] : 0u;
            __syncthreads();
            s_scan[tid] = v + add;
            __syncthreads();
        }
        uint32_t incl  = s_scan[tid];
        uint32_t above = (tid + 1 < NT) ? s_scan[tid + 1] : 0u;
        const uint32_t target = NSAMP;
        if (above < target && incl >= target) {
            uint32_t cgt = above;
            for (int k = 7; k >= 0; k--) {
                uint32_t h = hist[tid * 8 + k];
                if (cgt + h >= target) {
                    s_T = (uint32_t)(tid * 8 + k);
                    s_need = target - cgt;
                    break;
                }
                cgt += h;
            }
        }
        __syncthreads();
    }
    uint32_t T = s_T;
    uint32_t need = s_need;

    const float* img = real + b * PIX;
    float4* out = g_samp + b * NSAMP;

    // emit all entries from buckets strictly above T (strided for balance)
    for (uint32_t bucket = tid; bucket < 4096; bucket += NT) {
        if (bucket > T) {
            uint32_t n = hist[bucket];
            if (n > SLOTS) n = SLOTS;
            const uint32_t* bl = g_bl + (uint32_t)(b * 4096 + bucket) * SLOTS;
            for (uint32_t j = 0; j < n; j++) {
                uint32_t e = bl[j];
                uint32_t pos = atomicAdd(&s_cnt, 1u);
                uint32_t p = e & 16383u;
                out[pos] = pix_xyz4((int)p, img[p], s_par);
            }
        }
    }
    __syncthreads();

    // boundary bucket: sort desc by key, asc by index; take `need`
    if (tid == 0) {
        uint32_t n = hist[T];
        if (n > SLOTS) n = SLOTS;
        uint32_t arr[SLOTS];
        const uint32_t* bl = g_bl + (uint32_t)(b * 4096 + T) * SLOTS;
        for (uint32_t i = 0; i < n; i++) arr[i] = bl[i];
        for (uint32_t i = 1; i < n; i++) {
            uint32_t e = arr[i];
            int j = (int)i - 1;
            while (j >= 0) {
                uint32_t f = arr[j];
                bool before = ((e >> 14) > (f >> 14)) ||
                              ((e >> 14) == (f >> 14) && (e & 16383u) < (f & 16383u));
                if (before) { arr[j + 1] = f; j--; } else break;
            }
            arr[j + 1] = e;
        }
        uint32_t start = NSAMP - need;
        for (uint32_t i = 0; i < need && i < n; i++) {
            uint32_t p = arr[i] & 16383u;
            out[start + i] = pix_xyz4((int)p, img[p], s_par);
        }
    }
}

// ===== K_DIST: merged chamfer. blocks <512: vert pass; >=512: sample pass =====
__global__ void __launch_bounds__(256)
k_dist(const float* __restrict__ verts) {
    __shared__ ull   shbuf[4 * NPAIR];   // A: 4x64 packed samples; B: packed verts
    __shared__ float pm[256];

    int tid = threadIdx.x;

    if (blockIdx.x < 512) {
        // -------- A: per-vert min over a 128-sample slice --------
        int blk = blockIdx.x;
        int b = blk >> 3;
        int slice = blk & 7;
        ull* px = shbuf;        // 64
        ull* py = shbuf + 64;
        ull* pz = shbuf + 128;
        ull* pw = shbuf + 192;

        const float4* sp = g_samp + b * NSAMP + slice * 128;
        if (tid < 64) {
            float4 f0 = sp[2 * tid];
            float4 f1 = sp[2 * tid + 1];
            px[tid] = pk2(f0.x, f1.x);
            py[tid] = pk2(f0.y, f1.y);
            pz[tid] = pk2(f0.z, f1.z);
            pw[tid] = pk2(f0.w, f1.w);
        }
        __syncthreads();

        if (tid < 195) {
            const float* vb = verts + b * NV * 3;
            ull nx[4], ny[4], nz[4];
            float hw[4];
#pragma unroll
            for (int k = 0; k < 4; k++) {
                int v = 4 * tid + k;
                int vc = v < NV ? v : NV - 1;
                float x = vb[3 * vc], y = vb[3 * vc + 1], z = vb[3 * vc + 2];
                nx[k] = pk2(-x, -x);
                ny[k] = pk2(-y, -y);
                nz[k] = pk2(-z, -z);
                hw[k] = 0.5f * (x * x + y * y + z * z);
            }
            float ml[4] = {1e30f, 1e30f, 1e30f, 1e30f};
            float mh[4] = {1e30f, 1e30f, 1e30f, 1e30f};
#pragma unroll 2
            for (int i = 0; i < 64; i++) {
                ull X = px[i], Y = py[i], Z = pz[i], W = pw[i];
#pragma unroll
                for (int k = 0; k < 4; k++) {
                    float2 d = dot3p(nx[k], X, ny[k], Y, nz[k], Z, W);
                    ml[k] = fminf(ml[k], d.x);
                    mh[k] = fminf(mh[k], d.y);
                }
            }
#pragma unroll
            for (int k = 0; k < 4; k++) {
                int v = 4 * tid + k;
                if (v < NV) {
                    float val = 2.0f * (fminf(ml[k], mh[k]) + hw[k]) + 1.0f;
                    atomicMin(&g_vminb[b * NV + v], __float_as_uint(val));
                }
            }
        }
    } else {
        // -------- B: per-sample min over all verts (2 threads/sample) --------
        int blk = blockIdx.x - 512;
        int b = blk >> 3;
        int slice = blk & 7;
        ull* vx = shbuf;               // NPAIR each
        ull* vy = shbuf + NPAIR;
        ull* vz = shbuf + 2 * NPAIR;
        ull* vw = shbuf + 3 * NPAIR;

        const float* vb = verts + b * NV * 3;
        for (int j = tid; j < NPAIR; j += 256) {
            float ax = vb[6 * j],     ay = vb[6 * j + 1], az = vb[6 * j + 2];
            float bx = vb[6 * j + 3], by = vb[6 * j + 4], bz = vb[6 * j + 5];
            vx[j] = pk2(ax, bx);
            vy[j] = pk2(ay, by);
            vz[j] = pk2(az, bz);
            vw[j] = pk2(0.5f * (ax * ax + ay * ay + az * az),
                        0.5f * (bx * bx + by * by + bz * bz));
        }
        int sid = tid & 127;
        int half = tid >> 7;
        float4 me = g_samp[b * NSAMP + slice * 128 + sid];
        __syncthreads();

        ull mx = pk2(-me.x, -me.x);
        ull my = pk2(-me.y, -me.y);
        ull mz = pk2(-me.z, -me.z);
        float m = 1e30f;
        for (int j = half; j < NPAIR; j += 2) {
            float2 d = dot3p(mx, vx[j], my, vy[j], mz, vz[j], vw[j]);
            m = fminf(m, fminf(d.x, d.y));
        }
        pm[tid] = m;
        __syncthreads();
        if (tid < 128) {
            float mm = fminf(pm[tid], pm[tid + 128]);
            pm[tid] = 2.0f * (mm + me.w);
        }
        __syncthreads();
        for (int off = 64; off > 0; off >>= 1) {
            if (tid < off) pm[tid] += pm[tid + off];
            __syncthreads();
        }
        if (tid == 0) g_ssum[blk] = pm[0];
    }
}

// ===== K_RED1: per-batch sums (grid 64) =====
__global__ void __launch_bounds__(NT)
k_red1() {
    __shared__ float sred[NT];
    int b = blockIdx.x;
    int tid = threadIdx.x;

    float acc = 0.0f;
    for (int v = tid; v < NV; v += NT)
        acc += __uint_as_float(g_vminb[b * NV + v]) - 1.0f;
    sred[tid] = acc;
    __syncthreads();
    for (int off = NT / 2; off > 0; off >>= 1) {
        if (tid < off) sred[tid] += sred[tid + off];
        __syncthreads();
    }
    if (tid == 0) {
        g_batv[b] = sred[0];
        float s = 0.0f;
        for (int k = 0; k < 8; k++) s += g_ssum[b * 8 + k];
        g_bats[b] = s;
    }
}

// ===== K_RED2: final scalar (grid 1) =====
__global__ void __launch_bounds__(64)
k_red2(float* __restrict__ out) {
    __shared__ float sa[64], sv[64];
    int tid = threadIdx.x;
    sa[tid] = g_bats[tid];
    sv[tid] = g_batv[tid];
    __syncthreads();
    for (int off = 32; off > 0; off >>= 1) {
        if (tid < off) { sa[tid] += sa[tid + off]; sv[tid] += sv[tid + off]; }
        __syncthreads();
    }
    if (tid == 0)
        out[0] = sa[0] / (float)(NB * NSAMP) + sv[0] / (float)(NB * NV);
}

// ======================== launch ========================
extern "C" void kernel_launch(void* const* d_in, const int* in_sizes, int n_in,
                              void* d_out, int out_size) {
    const float* real   = (const float*)d_in[0];
    // d_in[1] synth unused, d_in[3] faces unused
    const float* verts  = (const float*)d_in[2];
    const float* center = (const float*)d_in[4];
    const float* Mmat   = (const float*)d_in[5];
    const float* cube   = (const float*)d_in[6];

    int nz = NB * 4096 + NVB;
    k_zero<<<(nz + NT - 1) / NT, NT>>>();
    kA<<<1024, 256>>>(real);
    kC<<<NB, NT>>>(real, center, Mmat, cube);
    k_dist<<<1024, 256>>>(verts);
    k_red1<<<NB, NT>>>();
    k_red2<<<1, 64>>>((float*)d_out);
}

// round 9
// speedup vs baseline: 1.3743x; 1.1160x over previous
#include <cuda_runtime.h>
#include <cstdint>

#define NT      512
#define PIX     16384
#define NB      64
#define NSAMP   1024
#define NV      778
#define NPAIR   389      // NV/2
#define SLOTS   32
#define NVB     (NB * NV)

typedef unsigned long long ull;

// ---------------- device scratch (no allocations allowed) ----------------
__device__ uint32_t g_hist[NB * 4096];           // per-batch bucket counts
__device__ uint32_t g_bl[NB * 4096 * SLOTS];     // bucket entry lists (32 MB)
__device__ float4   g_samp[NB * NSAMP];          // xyz + 0.5*|s|^2
__device__ uint32_t g_vminb[NVB];                // bits of d2min (>=0), atomicMin
__device__ ull      g_sacc;                      // fixed-point sum of sample mins

// ---------------- tf32 round-to-nearest-even (cuBLAS operand rounding) ----
__device__ __forceinline__ float tf32r(float x) {
    uint32_t u = __float_as_uint(x);
    uint32_t r = (u + 0xFFFu + ((u >> 13) & 1u)) & ~0x1FFFu;
    return __uint_as_float(r);
}

// ---------------- packed f32x2 helpers ----------------
__device__ __forceinline__ ull pk2(float lo, float hi) {
    ull r;
    asm("mov.b64 %0, {%1, %2};" : "=l"(r) : "f"(lo), "f"(hi));
    return r;
}

// (nx*X + (ny*Y + (nz*Z + W))) on both lanes, returns (lo, hi)
__device__ __forceinline__ float2 dot3p(ull nx, ull X, ull ny, ull Y,
                                        ull nz, ull Z, ull W) {
    float lo, hi;
    asm("{\n\t"
        ".reg .b64 t;\n\t"
        "fma.rn.f32x2 t, %2, %3, %4;\n\t"
        "fma.rn.f32x2 t, %5, %6, t;\n\t"
        "fma.rn.f32x2 t, %7, %8, t;\n\t"
        "mov.b64 {%0, %1}, t;\n\t"
        "}"
        : "=f"(lo), "=f"(hi)
        : "l"(nz), "l"(Z), "l"(W), "l"(ny), "l"(Y), "l"(nx), "l"(X));
    return make_float2(lo, hi);
}

// ------- threefry2x32-20, JAX partitionable counter-mode, key = (0,1) -----
__device__ __forceinline__ uint32_t rotl32(uint32_t x, uint32_t d) {
    return (x << d) | (x >> (32u - d));
}

__device__ __forceinline__ uint32_t threefry_bits_part(uint32_t e) {
    uint32_t x0 = 0u;
    uint32_t x1 = e;
    const uint32_t k0 = 0u, k1 = 1u;
    const uint32_t k2 = 0x1BD11BDAu ^ k0 ^ k1;
    x0 += k0; x1 += k1;
#define TF_RND(r) { x0 += x1; x1 = rotl32(x1, r) ^ x0; }
    TF_RND(13u) TF_RND(15u) TF_RND(26u) TF_RND(6u)
    x0 += k1; x1 += k2 + 1u;
    TF_RND(17u) TF_RND(29u) TF_RND(16u) TF_RND(24u)
    x0 += k2; x1 += k0 + 2u;
    TF_RND(13u) TF_RND(15u) TF_RND(26u) TF_RND(6u)
    x0 += k0; x1 += k1 + 3u;
    TF_RND(17u) TF_RND(29u) TF_RND(16u) TF_RND(24u)
    x0 += k1; x1 += k2 + 4u;
    TF_RND(13u) TF_RND(15u) TF_RND(26u) TF_RND(6u)
    x0 += k2; x1 += k0 + 5u;
#undef TF_RND
    return x0 ^ x1;
}

// ---------------- pixel -> normalized xyz (+ 0.5*|s|^2) ----------------
__device__ __forceinline__ float4 pix_xyz4(int p, float imgval, const float* sp) {
    float tj = 2.0f * (float)(p & 127) / 127.0f - 1.0f;
    float ti = 2.0f * (float)(p >> 7)  / 127.0f - 1.0f;
    float u = (tj + 1.0f) * 64.0f;
    float v = (ti + 1.0f) * 64.0f;
    float d = imgval * sp[11] + sp[8];
    float ut = tf32r(u), vt = tf32r(v);
    float uw = fmaf(sp[0], ut, fmaf(sp[1], vt, sp[2]));
    float vw = fmaf(sp[3], ut, fmaf(sp[4], vt, sp[5]));
    float x = (uw - 320.0f) * d / 588.03f;
    float y = (vw - 240.0f) * d / 587.07f;   // FLIP = 1
    float xn = (x - sp[6]) / sp[9];
    float yn = (y - sp[7]) / sp[10];
    float zn = (d - sp[8]) / sp[11];
    float hs = 0.5f * (xn * xn + yn * yn + zn * zn);
    return make_float4(xn, yn, zn, hs);
}

// ================= K0: zero histograms + init mins + accumulator ==========
__global__ void __launch_bounds__(NT)
k_zero() {
    int i = blockIdx.x * NT + threadIdx.x;
    if (i < NB * 4096) g_hist[i] = 0u;
    else if (i < NB * 4096 + NVB) g_vminb[i - NB * 4096] = 0x7F800000u;
    if (i == 0) g_sacc = 0ull;
}

// ===== KA: full-chip threefry + bucket binning (grid 1024) =====
__global__ void __launch_bounds__(256)
kA(const float* __restrict__ real) {
    int gt = blockIdx.x * 256 + threadIdx.x;   // 0..262143
#pragma unroll
    for (int k = 0; k < 4; k++) {
        uint32_t e = (uint32_t)gt + (uint32_t)k * 262144u;  // 0..2^20-1
        uint32_t bits = threefry_bits_part(e);
        bool valid = real[e] <= 0.99f;
        if (valid) {
            uint32_t sk = bits >> 9;             // 23-bit key
            uint32_t bucket = sk >> 11;          // top 12 bits
            uint32_t low11  = sk & 0x7FFu;
            uint32_t bi = (e >> 14) * 4096u + bucket;
            uint32_t pos = atomicAdd(&g_hist[bi], 1u);
            if (pos < SLOTS)
                g_bl[bi * SLOTS + pos] = (low11 << 14) | (e & 16383u);
        }
    }
}

// ===== KC: per-batch threshold + selected-pixel transform (grid 64) =====
__global__ void __launch_bounds__(NT)
kC(const float* __restrict__ real, const float* __restrict__ center,
   const float* __restrict__ Mmat, const float* __restrict__ cube) {
    __shared__ uint32_t hist[4096];
    __shared__ uint32_t wsum[16];
    __shared__ uint32_t woff[17];
    __shared__ float    s_par[12];
    __shared__ uint32_t s_T, s_need, s_cnt;

    int b = blockIdx.x;
    int tid = threadIdx.x;
    int lane = tid & 31;
    int wid = tid >> 5;

    if (tid == 0) {
        const float* Mb = Mmat + b * 9;
        double a00 = Mb[0], a01 = Mb[1], a02 = Mb[2];
        double a10 = Mb[3], a11 = Mb[4], a12 = Mb[5];
        double a20 = Mb[6], a21 = Mb[7], a22 = Mb[8];
        double det = a00 * (a11 * a22 - a12 * a21)
                   - a01 * (a10 * a22 - a12 * a20)
                   + a02 * (a10 * a21 - a11 * a20);
        double inv = 1.0 / det;
        s_par[0] = tf32r((float)( (a11 * a22 - a12 * a21) * inv));
        s_par[1] = tf32r((float)(-(a01 * a22 - a02 * a21) * inv));
        s_par[2] = tf32r((float)( (a01 * a12 - a02 * a11) * inv));
        s_par[3] = tf32r((float)(-(a10 * a22 - a12 * a20) * inv));
        s_par[4] = tf32r((float)( (a00 * a22 - a02 * a20) * inv));
        s_par[5] = tf32r((float)(-(a00 * a12 - a02 * a10) * inv));
        s_par[6] = center[b * 3 + 0];
        s_par[7] = center[b * 3 + 1];
        s_par[8] = center[b * 3 + 2];
        s_par[9]  = cube[b * 3 + 0] * 0.5f;
        s_par[10] = cube[b * 3 + 1] * 0.5f;
        s_par[11] = cube[b * 3 + 2] * 0.5f;
        s_cnt = 0;
    }
    for (int i = tid; i < 4096; i += NT) hist[i] = g_hist[b * 4096 + i];
    __syncthreads();

    // ---- threshold via shfl-based prefix over 512 per-thread sums ----
    uint32_t c = 0;
#pragma unroll
    for (int k = 0; k < 8; k++) c += hist[tid * 8 + k];
    uint32_t p = c;
#pragma unroll
    for (int d = 1; d < 32; d <<= 1) {
        uint32_t n = __shfl_up_sync(0xFFFFFFFFu, p, d);
        if (lane >= d) p += n;
    }
    if (lane == 31) wsum[wid] = p;
    __syncthreads();
    if (wid == 0) {
        uint32_t w = (lane < 16) ? wsum[lane] : 0u;
        uint32_t q = w;
#pragma unroll
        for (int d = 1; d < 16; d <<= 1) {
            uint32_t n = __shfl_up_sync(0xFFFFFFFFu, q, d);
            if (lane >= d) q += n;
        }
        if (lane < 16) woff[lane] = q - w;      // exclusive warp offsets
        if (lane == 15) woff[16] = q;           // grand total
    }
    __syncthreads();
    {
        uint32_t Pincl = p + woff[wid];
        uint32_t Tall = woff[16];
        uint32_t above = Tall - Pincl;          // count in buckets of threads > tid
        uint32_t S = above + c;
        const uint32_t target = NSAMP;
        if (above < target && S >= target) {
            uint32_t cgt = above;
            for (int k = 7; k >= 0; k--) {
                uint32_t h = hist[tid * 8 + k];
                if (cgt + h >= target) {
                    s_T = (uint32_t)(tid * 8 + k);
                    s_need = target - cgt;
                    break;
                }
                cgt += h;
            }
        }
    }
    __syncthreads();
    uint32_t T = s_T;
    uint32_t need = s_need;

    const float* img = real + b * PIX;
    float4* out = g_samp + b * NSAMP;

    // emit all entries from buckets strictly above T
    for (uint32_t bucket = tid; bucket < 4096; bucket += NT) {
        if (bucket > T) {
            uint32_t n = hist[bucket];
            if (n > SLOTS) n = SLOTS;
            const uint32_t* bl = g_bl + (uint32_t)(b * 4096 + bucket) * SLOTS;
            for (uint32_t j = 0; j < n; j++) {
                uint32_t e = bl[j];
                uint32_t pos = atomicAdd(&s_cnt, 1u);
                uint32_t pp = e & 16383u;
                out[pos] = pix_xyz4((int)pp, img[pp], s_par);
            }
        }
    }
    __syncthreads();

    // boundary bucket: sort desc by key, asc by index; take `need`
    if (tid == 0) {
        uint32_t n = hist[T];
        if (n > SLOTS) n = SLOTS;
        uint32_t arr[SLOTS];
        const uint32_t* bl = g_bl + (uint32_t)(b * 4096 + T) * SLOTS;
        for (uint32_t i = 0; i < n; i++) arr[i] = bl[i];
        for (uint32_t i = 1; i < n; i++) {
            uint32_t e = arr[i];
            int j = (int)i - 1;
            while (j >= 0) {
                uint32_t f = arr[j];
                bool before = ((e >> 14) > (f >> 14)) ||
                              ((e >> 14) == (f >> 14) && (e & 16383u) < (f & 16383u));
                if (before) { arr[j + 1] = f; j--; } else break;
            }
            arr[j + 1] = e;
        }
        uint32_t start = NSAMP - need;
        for (uint32_t i = 0; i < need && i < n; i++) {
            uint32_t pp = arr[i] & 16383u;
            out[start + i] = pix_xyz4((int)pp, img[pp], s_par);
        }
    }
}

// ===== K_DIST: blocks 0..255 vert pass (A); 256..383 sample pass (B) =====
__global__ void __launch_bounds__(256)
k_dist(const float* __restrict__ verts) {
    __shared__ ull   shbuf[4 * NPAIR];   // A: 4x128 packed samples; B: packed verts
    __shared__ float pm[256];

    int tid = threadIdx.x;

    if (blockIdx.x < 256) {
        // -------- A: per-vert min over a 256-sample chunk --------
        int blk = blockIdx.x;
        int b = blk >> 2;
        int chunk = blk & 3;
        ull* px = shbuf;         // 128
        ull* py = shbuf + 128;
        ull* pz = shbuf + 256;
        ull* pw = shbuf + 384;

        const float4* sp = g_samp + b * NSAMP + chunk * 256;
        if (tid < 128) {
            float4 f0 = sp[2 * tid];
            float4 f1 = sp[2 * tid + 1];
            px[tid] = pk2(f0.x, f1.x);
            py[tid] = pk2(f0.y, f1.y);
            pz[tid] = pk2(f0.z, f1.z);
            pw[tid] = pk2(f0.w, f1.w);
        }
        __syncthreads();

        if (tid < 195) {
            const float* vb = verts + b * NV * 3;
            ull nx[4], ny[4], nz[4];
            float hw[4];
            int vidx[4];
#pragma unroll
            for (int k = 0; k < 4; k++) {
                int v = 4 * tid + k;
                vidx[k] = v < NV ? v : NV - 1;
                float x = vb[3 * vidx[k]], y = vb[3 * vidx[k] + 1], z = vb[3 * vidx[k] + 2];
                nx[k] = pk2(-x, -x);
                ny[k] = pk2(-y, -y);
                nz[k] = pk2(-z, -z);
                hw[k] = 0.5f * (x * x + y * y + z * z);
            }
            float ml[4] = {1e30f, 1e30f, 1e30f, 1e30f};
            float mh[4] = {1e30f, 1e30f, 1e30f, 1e30f};
#pragma unroll 4
            for (int i = 0; i < 128; i++) {
                ull X = px[i], Y = py[i], Z = pz[i], W = pw[i];
#pragma unroll
                for (int k = 0; k < 4; k++) {
                    float2 d = dot3p(nx[k], X, ny[k], Y, nz[k], Z, W);
                    ml[k] = fminf(ml[k], d.x);
                    mh[k] = fminf(mh[k], d.y);
                }
            }
#pragma unroll
            for (int k = 0; k < 4; k++) {
                if (4 * tid + k < NV) {
                    float val = 2.0f * (fminf(ml[k], mh[k]) + hw[k]);  // >= 0
                    atomicMin(&g_vminb[b * NV + vidx[k]], __float_as_uint(val));
                }
            }
        }
    } else {
        // -------- B: per-sample min over ALL verts, 2 samples/thread --------
        int blk = blockIdx.x - 256;
        int b = blk >> 1;
        int half = blk & 1;
        ull* vx = shbuf;               // NPAIR each
        ull* vy = shbuf + NPAIR;
        ull* vz = shbuf + 2 * NPAIR;
        ull* vw = shbuf + 3 * NPAIR;

        const float* vb = verts + b * NV * 3;
        for (int j = tid; j < NPAIR; j += 256) {
            float ax = vb[6 * j],     ay = vb[6 * j + 1], az = vb[6 * j + 2];
            float bx = vb[6 * j + 3], by = vb[6 * j + 4], bz = vb[6 * j + 5];
            vx[j] = pk2(ax, bx);
            vy[j] = pk2(ay, by);
            vz[j] = pk2(az, bz);
            vw[j] = pk2(0.5f * (ax * ax + ay * ay + az * az),
                        0.5f * (bx * bx + by * by + bz * bz));
        }
        int s0 = half * 512 + tid;
        int s1 = half * 512 + 256 + tid;
        float4 me0 = g_samp[b * NSAMP + s0];
        float4 me1 = g_samp[b * NSAMP + s1];
        __syncthreads();

        ull ax0 = pk2(-me0.x, -me0.x), ay0 = pk2(-me0.y, -me0.y), az0 = pk2(-me0.z, -me0.z);
        ull ax1 = pk2(-me1.x, -me1.x), ay1 = pk2(-me1.y, -me1.y), az1 = pk2(-me1.z, -me1.z);
        float m0a = 1e30f, m0b = 1e30f, m1a = 1e30f, m1b = 1e30f;
#pragma unroll 4
        for (int j = 0; j < NPAIR; j++) {
            ull X = vx[j], Y = vy[j], Z = vz[j], W = vw[j];
            float2 d0 = dot3p(ax0, X, ay0, Y, az0, Z, W);
            float2 d1 = dot3p(ax1, X, ay1, Y, az1, Z, W);
            m0a = fminf(m0a, d0.x); m0b = fminf(m0b, d0.y);
            m1a = fminf(m1a, d1.x); m1b = fminf(m1b, d1.y);
        }
        float sum = 2.0f * (fminf(m0a, m0b) + me0.w)
                  + 2.0f * (fminf(m1a, m1b) + me1.w);

        pm[tid] = sum;
        __syncthreads();
        for (int off = 128; off > 0; off >>= 1) {
            if (tid < off) pm[tid] += pm[tid + off];
            __syncthreads();
        }
        if (tid == 0) {
            // deterministic fixed-point accumulation (integer add commutes)
            ull fx = (ull)(double)((double)pm[0] * 4294967296.0);
            atomicAdd(&g_sacc, fx);
        }
    }
}

// ===== K_RED: final scalar (grid 1) =====
__global__ void __launch_bounds__(NT)
k_red(float* __restrict__ out) {
    __shared__ float sred[NT];
    int tid = threadIdx.x;

    float acc = 0.0f;
    for (int i = tid; i < NVB; i += NT)
        acc += __uint_as_float(g_vminb[i]);
    sred[tid] = acc;
    __syncthreads();
    for (int off = NT / 2; off > 0; off >>= 1) {
        if (tid < off) sred[tid] += sred[tid + off];
        __syncthreads();
    }
    if (tid == 0) {
        double s = (double)g_sacc * (1.0 / 4294967296.0);
        out[0] = (float)(s / (double)(NB * NSAMP)) +
                 sred[0] / (float)(NB * NV);
    }
}

// ======================== launch ========================
extern "C" void kernel_launch(void* const* d_in, const int* in_sizes, int n_in,
                              void* d_out, int out_size) {
    const float* real   = (const float*)d_in[0];
    // d_in[1] synth unused, d_in[3] faces unused
    const float* verts  = (const float*)d_in[2];
    const float* center = (const float*)d_in[4];
    const float* Mmat   = (const float*)d_in[5];
    const float* cube   = (const float*)d_in[6];

    int nz = NB * 4096 + NVB;
    k_zero<<<(nz + NT - 1) / NT, NT>>>();
    kA<<<1024, 256>>>(real);
    kC<<<NB, NT>>>(real, center, Mmat, cube);
    k_dist<<<384, 256>>>(verts);
    k_red<<<1, NT>>>((float*)d_out);
}